// round 1
// baseline (speedup 1.0000x reference)
#include <cuda_runtime.h>
#include <cstdint>

#define BATCH 4096
#define IN    2048
#define HID   8192
#define NCLS  1000

// Global per-row argmax state: packed (ordered_float(val) << 32) | (HID-1-col).
// atomicMax over this key == max value, ties broken toward SMALLEST column
// (matches jnp.argmax first-occurrence semantics).
__device__ unsigned long long g_best[BATCH];

__global__ void init_best_kernel() {
    int i = blockIdx.x * blockDim.x + threadIdx.x;
    if (i < BATCH) g_best[i] = 0ULL;
}

__device__ __forceinline__ unsigned long long pack_key(float v, int col) {
    unsigned int b = __float_as_uint(v);
    // map float to order-preserving unsigned int
    b = (b & 0x80000000u) ? ~b : (b | 0x80000000u);
    return ((unsigned long long)b << 32) | (unsigned int)((HID - 1) - col);
}

// Fused GEMM + row-argmax.
// C[b][h] = sum_k x[b][k] * Wk[h][k]   (x: [B,IN] row-major, Wk: [HID,IN] row-major)
// Tile: 128x128x16, 256 threads, 8x8 per-thread microtile.
__global__ __launch_bounds__(256, 2)
void gemm_argmax_kernel(const float* __restrict__ x, const float* __restrict__ Wk) {
    __shared__ float As[16][128];                 // As[k][m]
    __shared__ float Bs[16][128];                 // Bs[k][n]
    __shared__ unsigned long long red[128];

    const int tid = threadIdx.x;
    const int tx  = tid & 15;          // 0..15 -> n
    const int ty  = tid >> 4;          // 0..15 -> m
    const int bm0 = blockIdx.y * 128;
    const int bn0 = blockIdx.x * 128;

    // global-load mapping: each thread loads 2 float4 per matrix per k-tile
    const int lr = tid >> 2;           // 0..63 (row within tile, plus +64 sibling)
    const int lc = (tid & 3) * 4;      // 0,4,8,12 (col within 16-wide k-slab)

    const float* __restrict__ xA = x  + (size_t)bm0 * IN;
    const float* __restrict__ wB = Wk + (size_t)bn0 * IN;

    float acc[8][8];
#pragma unroll
    for (int i = 0; i < 8; i++)
#pragma unroll
        for (int j = 0; j < 8; j++) acc[i][j] = 0.0f;

    for (int k0 = 0; k0 < IN; k0 += 16) {
        float4 a0 = *(const float4*)(xA + (size_t)(lr)      * IN + k0 + lc);
        float4 a1 = *(const float4*)(xA + (size_t)(lr + 64) * IN + k0 + lc);
        float4 b0 = *(const float4*)(wB + (size_t)(lr)      * IN + k0 + lc);
        float4 b1 = *(const float4*)(wB + (size_t)(lr + 64) * IN + k0 + lc);

        __syncthreads();   // previous tile fully consumed before overwrite

        As[lc + 0][lr]      = a0.x; As[lc + 1][lr]      = a0.y;
        As[lc + 2][lr]      = a0.z; As[lc + 3][lr]      = a0.w;
        As[lc + 0][lr + 64] = a1.x; As[lc + 1][lr + 64] = a1.y;
        As[lc + 2][lr + 64] = a1.z; As[lc + 3][lr + 64] = a1.w;

        Bs[lc + 0][lr]      = b0.x; Bs[lc + 1][lr]      = b0.y;
        Bs[lc + 2][lr]      = b0.z; Bs[lc + 3][lr]      = b0.w;
        Bs[lc + 0][lr + 64] = b1.x; Bs[lc + 1][lr + 64] = b1.y;
        Bs[lc + 2][lr + 64] = b1.z; Bs[lc + 3][lr + 64] = b1.w;

        __syncthreads();

#pragma unroll
        for (int kk = 0; kk < 16; kk++) {
            float4 av0 = *(const float4*)&As[kk][ty * 8];
            float4 av1 = *(const float4*)&As[kk][ty * 8 + 4];
            float4 bv0 = *(const float4*)&Bs[kk][tx * 8];
            float4 bv1 = *(const float4*)&Bs[kk][tx * 8 + 4];
            float a[8] = {av0.x, av0.y, av0.z, av0.w, av1.x, av1.y, av1.z, av1.w};
            float b[8] = {bv0.x, bv0.y, bv0.z, bv0.w, bv1.x, bv1.y, bv1.z, bv1.w};
#pragma unroll
            for (int i = 0; i < 8; i++)
#pragma unroll
                for (int j = 0; j < 8; j++)
                    acc[i][j] = fmaf(a[i], b[j], acc[i][j]);
        }
    }

    // ---- fused argmax epilogue ----
    for (int i = tid; i < 128; i += 256) red[i] = 0ULL;
    __syncthreads();

#pragma unroll
    for (int i = 0; i < 8; i++) {
        float best = acc[i][0];
        int   bj   = 0;
#pragma unroll
        for (int j = 1; j < 8; j++) {
            if (acc[i][j] > best) { best = acc[i][j]; bj = j; }  // strict > keeps lowest col on tie
        }
        unsigned long long key = pack_key(best, bn0 + tx * 8 + bj);
        atomicMax(&red[ty * 8 + i], key);
    }
    __syncthreads();

    for (int i = tid; i < 128; i += 256)
        atomicMax(&g_best[bm0 + i], red[i]);
}

// out[b][c] = Wg[c][idx[b]]
__global__ void gather_kernel(const float* __restrict__ Wg, float* __restrict__ out) {
    __shared__ int s_idx;
    const int b = blockIdx.y;
    if (threadIdx.x == 0) {
        unsigned long long key = g_best[b];
        s_idx = (HID - 1) - (int)(unsigned int)(key & 0xFFFFFFFFu);
    }
    __syncthreads();
    const int c = blockIdx.x * blockDim.x + threadIdx.x;
    if (c < NCLS)
        out[(size_t)b * NCLS + c] = Wg[(size_t)c * HID + s_idx];
}

extern "C" void kernel_launch(void* const* d_in, const int* in_sizes, int n_in,
                              void* d_out, int out_size) {
    const float* x  = (const float*)d_in[0];   // [BATCH, IN]
    const float* Wk = (const float*)d_in[1];   // [HID, IN]
    const float* Wg = (const float*)d_in[2];   // [NCLS, HID]
    float* out = (float*)d_out;                // [BATCH, NCLS]

    init_best_kernel<<<(BATCH + 255) / 256, 256>>>();

    dim3 ggrid(HID / 128, BATCH / 128);        // (64, 32)
    gemm_argmax_kernel<<<ggrid, 256>>>(x, Wk);

    dim3 sgrid((NCLS + 255) / 256, BATCH);     // (4, 4096)
    gather_kernel<<<sgrid, 256>>>(Wg, out);
}

// round 4
// speedup vs baseline: 2.4160x; 2.4160x over previous
#include <cuda_runtime.h>
#include <cuda_fp16.h>
#include <cstdint>

#define BATCH 4096
#define IN    2048
#define HID   8192
#define NCLS  1000
#define KP    6144          // K' = 3 * IN (hi|lo|hi split)
#define NCH   96            // KP / 64 k-chunks
#define ST    3             // pipeline stages

// ---------------- scratch (static device arrays; no allocation) -------------
__device__ __align__(128) __half g_X[(size_t)BATCH * KP];   // [B,  KP]  = [hiX | loX | hiX]
__device__ __align__(128) __half g_W[(size_t)HID   * KP];   // [HID,KP]  = [hiW | hiW | loW]
__device__ unsigned long long g_best[BATCH];

// ---------------- helpers ----------------------------------------------------
__device__ __forceinline__ uint32_t smem_u32(const void* p) {
    uint32_t a;
    asm("{ .reg .u64 t; cvta.to.shared.u64 t, %1; cvt.u32.u64 %0, t; }" : "=r"(a) : "l"(p));
    return a;
}
__device__ __forceinline__ void cp_async16(uint32_t dst, const void* src) {
    asm volatile("cp.async.cg.shared.global [%0], [%1], 16;" :: "r"(dst), "l"(src));
}
#define CP_COMMIT() asm volatile("cp.async.commit_group;" ::: "memory")
#define CP_WAIT(n)  asm volatile("cp.async.wait_group %0;" :: "n"(n) : "memory")

#define LDSM4(r0, r1, r2, r3, a)                                             \
    asm volatile("ldmatrix.sync.aligned.m8n8.x4.shared.b16 {%0,%1,%2,%3}, [%4];" \
                 : "=r"(r0), "=r"(r1), "=r"(r2), "=r"(r3) : "r"(a))

__device__ __forceinline__ void mma16816(float* c, const uint32_t* a, const uint32_t* b) {
    asm volatile(
        "mma.sync.aligned.m16n8k16.row.col.f32.f16.f16.f32 "
        "{%0,%1,%2,%3}, {%4,%5,%6,%7}, {%8,%9}, {%0,%1,%2,%3};"
        : "+f"(c[0]), "+f"(c[1]), "+f"(c[2]), "+f"(c[3])
        : "r"(a[0]), "r"(a[1]), "r"(a[2]), "r"(a[3]), "r"(b[0]), "r"(b[1]));
}

__device__ __forceinline__ uint32_t sw128(uint32_t off) { return off ^ ((off >> 3) & 0x70); }

__device__ __forceinline__ unsigned long long pack_key(float v, int col) {
    unsigned int b = __float_as_uint(v);
    b = (b & 0x80000000u) ? ~b : (b | 0x80000000u);   // order-preserving map
    return ((unsigned long long)b << 32) | (unsigned int)((HID - 1) - col);
}

// ---------------- small kernels ----------------------------------------------
__global__ void init_best_kernel() {
    int i = blockIdx.x * blockDim.x + threadIdx.x;
    if (i < BATCH) g_best[i] = 0ULL;
}

__global__ void convert_x_kernel(const float* __restrict__ x) {
    int i = blockIdx.x * blockDim.x + threadIdx.x;
    if (i >= BATCH * IN) return;
    int b = i / IN, k = i - b * IN;
    float v = x[i];
    __half hi = __float2half_rn(v);
    __half lo = __float2half_rn(v - __half2float(hi));
    size_t ro = (size_t)b * KP;
    g_X[ro + k]          = hi;
    g_X[ro + IN + k]     = lo;
    g_X[ro + 2 * IN + k] = hi;
}

__global__ void convert_w_kernel(const float* __restrict__ w) {
    int i = blockIdx.x * blockDim.x + threadIdx.x;
    if (i >= HID * IN) return;
    int h = i / IN, k = i - h * IN;
    float v = w[i];
    __half hi = __float2half_rn(v);
    __half lo = __float2half_rn(v - __half2float(hi));
    size_t ro = (size_t)h * KP;
    g_W[ro + k]          = hi;
    g_W[ro + IN + k]     = hi;
    g_W[ro + 2 * IN + k] = lo;
}

// ---------------- fused mma.sync GEMM + argmax ---------------------------------
// C[b][h] = sum_k X'[b][k] * W'[h][k], 128x128 tile, K-chunks of 64 halves,
// 3-stage cp.async pipeline, SW128-swizzled smem, 8 warps (warp tile 64x32).
__global__ __launch_bounds__(256, 1)
void gemm_argmax_mma() {
    extern __shared__ char smem[];
    const int tid  = threadIdx.x;
    const int lane = tid & 31;
    const int wid  = tid >> 5;
    const int warp_m = wid & 1;   // 0..1  -> 64-row slab
    const int warp_n = wid >> 1;  // 0..3  -> 32-col slab

    // supertile rasterization for L2 reuse: 8 N-tiles per group
    int bid = blockIdx.x;
    int group = bid >> 8, within = bid & 255;
    int ncol = (group << 3) | (within & 7);   // 0..63
    int mrow = within >> 3;                   // 0..31
    const int bm0 = mrow * 128;
    const int bn0 = ncol * 128;

    uint32_t sb    = smem_u32(smem);
    uint32_t tiles = (sb + 1023) & ~1023u;    // stages: [A 16KB | B 16KB] x 3

    // ---- global->shared load mapping: 4 x 16B per matrix per chunk ----
    const int row_l = tid >> 3;               // 0..31
    const int colb  = (tid & 7) * 16;         // byte offset in 128B row
    uint32_t dsw[4];
#pragma unroll
    for (int i = 0; i < 4; i++) dsw[i] = sw128((row_l + 32 * i) * 128 + colb);

    const __half* pA = g_X + (size_t)(bm0 + row_l) * KP + (colb >> 1);
    const __half* pB = g_W + (size_t)(bn0 + row_l) * KP + (colb >> 1);

    // ---- ldmatrix per-thread swizzled offsets, one per kk (swizzle does NOT
    //      commute with +32B column steps; row steps of +2048B are safe) ----
    const uint32_t aRow = warp_m * 64 + (lane & 15);
    const uint32_t aCol = (lane >> 4) << 4;                                // 0 / 16 B
    const uint32_t bRow = warp_n * 32 + (lane & 7) + ((lane >> 4) << 3);
    const uint32_t bCol = ((lane >> 3) & 1) << 4;                          // 0 / 16 B
    uint32_t aSwk[4], bSwk[4];
#pragma unroll
    for (int kk = 0; kk < 4; kk++) {
        aSwk[kk] = sw128(aRow * 128 + aCol + kk * 32);
        bSwk[kk] = sw128(bRow * 128 + bCol + kk * 32);
    }

    float acc[4][4][4];
#pragma unroll
    for (int i = 0; i < 4; i++)
#pragma unroll
        for (int j = 0; j < 4; j++)
#pragma unroll
            for (int k = 0; k < 4; k++) acc[i][j][k] = 0.0f;

    // ---- prologue: issue chunks 0..ST-2 ----
#pragma unroll
    for (int p = 0; p < ST - 1; p++) {
        uint32_t As = tiles + p * 32768u;
        uint32_t Bs = As + 16384u;
        size_t ko = (size_t)p * 64;
#pragma unroll
        for (int i = 0; i < 4; i++) cp_async16(As + dsw[i], pA + (size_t)i * 32 * KP + ko);
#pragma unroll
        for (int i = 0; i < 4; i++) cp_async16(Bs + dsw[i], pB + (size_t)i * 32 * KP + ko);
        CP_COMMIT();
    }

    for (int c = 0; c < NCH; c++) {
        const int s = c % ST;
        __syncthreads();                      // chunk c-1 fully consumed before stage reuse
        if (c + ST - 1 < NCH) {
            const int cs = (c + ST - 1) % ST;
            uint32_t As = tiles + cs * 32768u;
            uint32_t Bs = As + 16384u;
            size_t ko = (size_t)(c + ST - 1) * 64;
#pragma unroll
            for (int i = 0; i < 4; i++) cp_async16(As + dsw[i], pA + (size_t)i * 32 * KP + ko);
#pragma unroll
            for (int i = 0; i < 4; i++) cp_async16(Bs + dsw[i], pB + (size_t)i * 32 * KP + ko);
        }
        CP_COMMIT();                          // always commit: keeps group arithmetic uniform
        CP_WAIT(ST - 1);                      // chunk c's group complete
        __syncthreads();

        const uint32_t aBase = tiles + s * 32768u;
        const uint32_t bBase = tiles + s * 32768u + 16384u;

#pragma unroll
        for (int kk = 0; kk < 4; kk++) {
            uint32_t a[4][4];
#pragma unroll
            for (int im = 0; im < 4; im++)
                LDSM4(a[im][0], a[im][1], a[im][2], a[im][3],
                      aBase + aSwk[kk] + im * 2048u);
            uint32_t b[4][2];
#pragma unroll
            for (int in2 = 0; in2 < 2; in2++) {
                uint32_t r0, r1, r2, r3;
                LDSM4(r0, r1, r2, r3, bBase + bSwk[kk] + in2 * 2048u);
                b[2 * in2][0] = r0; b[2 * in2][1] = r1;
                b[2 * in2 + 1][0] = r2; b[2 * in2 + 1][1] = r3;
            }
#pragma unroll
            for (int im = 0; im < 4; im++)
#pragma unroll
                for (int jn = 0; jn < 4; jn++)
                    mma16816(acc[im][jn], a[im], b[jn]);
        }
    }

    // ---- fused argmax epilogue ----
    __syncthreads();
    unsigned long long* red = (unsigned long long*)smem;   // reuse tile smem
    if (tid < 128) red[tid] = 0ULL;
    __syncthreads();

    // acc[im][jn][k]: row = warp_m*64 + im*16 + (lane>>2) + (k>=2 ? 8 : 0)
    //                col = bn0 + warp_n*32 + jn*8 + (lane&3)*2 + (k&1)
#pragma unroll
    for (int im = 0; im < 4; im++) {
#pragma unroll
        for (int half = 0; half < 2; half++) {
            unsigned long long key = 0ULL;
#pragma unroll
            for (int jn = 0; jn < 4; jn++) {
#pragma unroll
                for (int e = 0; e < 2; e++) {
                    int k = half * 2 + e;
                    int col = bn0 + warp_n * 32 + jn * 8 + (lane & 3) * 2 + e;
                    unsigned long long kk2 = pack_key(acc[im][jn][k], col);
                    if (kk2 > key) key = kk2;
                }
            }
            int row = warp_m * 64 + im * 16 + (lane >> 2) + half * 8;
            atomicMax(&red[row], key);
        }
    }
    __syncthreads();
    if (tid < 128) atomicMax(&g_best[bm0 + tid], red[tid]);
}

// out[b][c] = Wg[c][idx[b]]
__global__ void gather_kernel(const float* __restrict__ Wg, float* __restrict__ out) {
    __shared__ int s_idx;
    const int b = blockIdx.y;
    if (threadIdx.x == 0) {
        unsigned long long key = g_best[b];
        s_idx = (HID - 1) - (int)(unsigned int)(key & 0xFFFFFFFFu);
    }
    __syncthreads();
    const int c = blockIdx.x * blockDim.x + threadIdx.x;
    if (c < NCLS)
        out[(size_t)b * NCLS + c] = Wg[(size_t)c * HID + s_idx];
}

// ---------------- launch -------------------------------------------------------
extern "C" void kernel_launch(void* const* d_in, const int* in_sizes, int n_in,
                              void* d_out, int out_size) {
    const float* x  = (const float*)d_in[0];   // [BATCH, IN]
    const float* Wk = (const float*)d_in[1];   // [HID, IN]
    const float* Wg = (const float*)d_in[2];   // [NCLS, HID]
    float* out = (float*)d_out;                // [BATCH, NCLS]

    const int SMEM_BYTES = 1024 + ST * 32768;  // align slack + 3 stages
    cudaFuncSetAttribute(gemm_argmax_mma, cudaFuncAttributeMaxDynamicSharedMemorySize, SMEM_BYTES);

    init_best_kernel<<<(BATCH + 255) / 256, 256>>>();
    convert_x_kernel<<<(BATCH * IN + 255) / 256, 256>>>(x);
    convert_w_kernel<<<(HID * IN + 255) / 256, 256>>>(Wk);

    gemm_argmax_mma<<<(BATCH / 128) * (HID / 128), 256, SMEM_BYTES>>>();

    dim3 sgrid((NCLS + 255) / 256, BATCH);
    gather_kernel<<<sgrid, 256>>>(Wg, out);
}

// round 5
// speedup vs baseline: 2.7613x; 1.1430x over previous
#include <cuda_runtime.h>
#include <cuda_fp16.h>
#include <cstdint>

#define BATCH 4096
#define IN    2048
#define HID   8192
#define NCLS  1000
#define KP    6144          // K' = 3 * IN (hi|lo|hi split)
#define NCH   96            // KP / 64 k-chunks
#define ST    3             // pipeline stages
#define STAGE_BYTES 49152u  // A 32KB + B 16KB

// ---------------- scratch (static device arrays; no allocation) -------------
__device__ __align__(128) __half g_X[(size_t)BATCH * KP];   // [B,  KP]  = [hiX | loX | hiX]
__device__ __align__(128) __half g_W[(size_t)HID   * KP];   // [HID,KP]  = [hiW | hiW | loW]
__device__ unsigned long long g_best[BATCH];

// ---------------- helpers ----------------------------------------------------
__device__ __forceinline__ uint32_t smem_u32(const void* p) {
    uint32_t a;
    asm("{ .reg .u64 t; cvta.to.shared.u64 t, %1; cvt.u32.u64 %0, t; }" : "=r"(a) : "l"(p));
    return a;
}
__device__ __forceinline__ void cp_async16(uint32_t dst, const void* src) {
    asm volatile("cp.async.cg.shared.global [%0], [%1], 16;" :: "r"(dst), "l"(src));
}
#define CP_COMMIT() asm volatile("cp.async.commit_group;" ::: "memory")
#define CP_WAIT(n)  asm volatile("cp.async.wait_group %0;" :: "n"(n) : "memory")

#define LDSM4(r0, r1, r2, r3, a)                                             \
    asm volatile("ldmatrix.sync.aligned.m8n8.x4.shared.b16 {%0,%1,%2,%3}, [%4];" \
                 : "=r"(r0), "=r"(r1), "=r"(r2), "=r"(r3) : "r"(a))

__device__ __forceinline__ void mma16816(float* c, const uint32_t* a, const uint32_t* b) {
    asm volatile(
        "mma.sync.aligned.m16n8k16.row.col.f32.f16.f16.f32 "
        "{%0,%1,%2,%3}, {%4,%5,%6,%7}, {%8,%9}, {%0,%1,%2,%3};"
        : "+f"(c[0]), "+f"(c[1]), "+f"(c[2]), "+f"(c[3])
        : "r"(a[0]), "r"(a[1]), "r"(a[2]), "r"(a[3]), "r"(b[0]), "r"(b[1]));
}

__device__ __forceinline__ uint32_t sw128(uint32_t off) { return off ^ ((off >> 3) & 0x70); }

__device__ __forceinline__ unsigned long long pack_key(float v, int col) {
    unsigned int b = __float_as_uint(v);
    b = (b & 0x80000000u) ? ~b : (b | 0x80000000u);   // order-preserving map
    return ((unsigned long long)b << 32) | (unsigned int)((HID - 1) - col);
}

// ---------------- small kernels ----------------------------------------------
__global__ void init_best_kernel() {
    int i = blockIdx.x * blockDim.x + threadIdx.x;
    if (i < BATCH) g_best[i] = 0ULL;
}

__global__ void convert_x_kernel(const float* __restrict__ x) {
    int i = blockIdx.x * blockDim.x + threadIdx.x;
    if (i >= BATCH * IN) return;
    int b = i / IN, k = i - b * IN;
    float v = x[i];
    __half hi = __float2half_rn(v);
    __half lo = __float2half_rn(v - __half2float(hi));
    size_t ro = (size_t)b * KP;
    g_X[ro + k]          = hi;
    g_X[ro + IN + k]     = lo;
    g_X[ro + 2 * IN + k] = hi;
}

__global__ void convert_w_kernel(const float* __restrict__ w) {
    int i = blockIdx.x * blockDim.x + threadIdx.x;
    if (i >= HID * IN) return;
    int h = i / IN, k = i - h * IN;
    float v = w[i];
    __half hi = __float2half_rn(v);
    __half lo = __float2half_rn(v - __half2float(hi));
    size_t ro = (size_t)h * KP;
    g_W[ro + k]          = hi;
    g_W[ro + IN + k]     = hi;
    g_W[ro + 2 * IN + k] = lo;
}

// ---------------- fused mma.sync GEMM + argmax ---------------------------------
// C[b][h] = sum_k X'[b][k] * W'[h][k].  CTA tile 256(M) x 128(N), K-chunks of 64
// halves, 3-stage cp.async pipeline (ONE barrier per chunk), SW128 smem,
// 8 warps in 4(m) x 2(n) grid, warp tile 64x64 (4x8 m16n8k16 micro-tiles).
__global__ __launch_bounds__(256, 1)
void gemm_argmax_mma() {
    extern __shared__ char smem[];
    const int tid  = threadIdx.x;
    const int lane = tid & 31;
    const int wid  = tid >> 5;
    const int warp_m = wid >> 1;  // 0..3 -> 64-row slab
    const int warp_n = wid & 1;   // 0..1 -> 64-col slab

    // supertile rasterization for L2 reuse: 8 N-tiles per group, 16 M-rows
    int bid = blockIdx.x;
    int group = bid >> 7, within = bid & 127;
    int ncol = (group << 3) | (within & 7);   // 0..63
    int mrow = within >> 3;                   // 0..15
    const int bm0 = mrow * 256;
    const int bn0 = ncol * 128;

    uint32_t sb    = smem_u32(smem);
    uint32_t tiles = (sb + 1023) & ~1023u;    // stages: [A 32KB | B 16KB] x 3

    // ---- global->shared mapping: A 8 x 16B, B 4 x 16B per thread per chunk ----
    const int row_l = tid >> 3;               // 0..31
    const int colb  = (tid & 7) * 16;         // byte offset in 128B row
    uint32_t dswA[8], dswB[4];
#pragma unroll
    for (int i = 0; i < 8; i++) dswA[i] = sw128((row_l + 32 * i) * 128 + colb);
#pragma unroll
    for (int i = 0; i < 4; i++) dswB[i] = dswA[i];

    const __half* pA = g_X + (size_t)(bm0 + row_l) * KP + (colb >> 1);
    const __half* pB = g_W + (size_t)(bn0 + row_l) * KP + (colb >> 1);

    // ---- ldmatrix per-thread swizzled offsets, one per kk (swizzle does not
    //      commute with +32B column steps; +2048B row steps are safe) ----
    const uint32_t aRow = warp_m * 64 + (lane & 15);
    const uint32_t aCol = (lane >> 4) << 4;                                // 0 / 16 B
    const uint32_t bRow = warp_n * 64 + (lane & 7) + ((lane >> 4) << 3);
    const uint32_t bCol = ((lane >> 3) & 1) << 4;                          // 0 / 16 B
    uint32_t aSwk[4], bSwk[4];
#pragma unroll
    for (int kk = 0; kk < 4; kk++) {
        aSwk[kk] = sw128(aRow * 128 + aCol + kk * 32);
        bSwk[kk] = sw128(bRow * 128 + bCol + kk * 32);
    }

    float acc[4][8][4];
#pragma unroll
    for (int i = 0; i < 4; i++)
#pragma unroll
        for (int j = 0; j < 8; j++)
#pragma unroll
            for (int k = 0; k < 4; k++) acc[i][j][k] = 0.0f;

    // ---- prologue: issue chunks 0..ST-2 ----
#pragma unroll
    for (int p = 0; p < ST - 1; p++) {
        uint32_t As = tiles + p * STAGE_BYTES;
        uint32_t Bs = As + 32768u;
        size_t ko = (size_t)p * 64;
#pragma unroll
        for (int i = 0; i < 8; i++) cp_async16(As + dswA[i], pA + (size_t)i * 32 * KP + ko);
#pragma unroll
        for (int i = 0; i < 4; i++) cp_async16(Bs + dswB[i], pB + (size_t)i * 32 * KP + ko);
        CP_COMMIT();
    }

    for (int c = 0; c < NCH; c++) {
        const int s = c % ST;

        // chunk c complete (commits outstanding: c, c+1 at most)
        if (c + 2 < NCH) CP_WAIT(1); else CP_WAIT(0);
        __syncthreads();   // all warps done with chunk c-1 => stage (c+2)%ST free

        if (c + 2 < NCH) {
            const int cs = (c + 2) % ST;
            uint32_t As = tiles + cs * STAGE_BYTES;
            uint32_t Bs = As + 32768u;
            size_t ko = (size_t)(c + 2) * 64;
#pragma unroll
            for (int i = 0; i < 8; i++) cp_async16(As + dswA[i], pA + (size_t)i * 32 * KP + ko);
#pragma unroll
            for (int i = 0; i < 4; i++) cp_async16(Bs + dswB[i], pB + (size_t)i * 32 * KP + ko);
            CP_COMMIT();
        }

        const uint32_t aBase = tiles + s * STAGE_BYTES;
        const uint32_t bBase = aBase + 32768u;

#pragma unroll
        for (int kk = 0; kk < 4; kk++) {
            uint32_t a[4][4];
#pragma unroll
            for (int im = 0; im < 4; im++)
                LDSM4(a[im][0], a[im][1], a[im][2], a[im][3],
                      aBase + aSwk[kk] + im * 2048u);
            uint32_t b[8][2];
#pragma unroll
            for (int in2 = 0; in2 < 4; in2++) {
                uint32_t r0, r1, r2, r3;
                LDSM4(r0, r1, r2, r3, bBase + bSwk[kk] + in2 * 2048u);
                b[2 * in2][0] = r0;     b[2 * in2][1] = r1;
                b[2 * in2 + 1][0] = r2; b[2 * in2 + 1][1] = r3;
            }
#pragma unroll
            for (int im = 0; im < 4; im++)
#pragma unroll
                for (int jn = 0; jn < 8; jn++)
                    mma16816(acc[im][jn], a[im], b[jn]);
        }
    }

    // ---- fused argmax epilogue ----
    __syncthreads();
    unsigned long long* red = (unsigned long long*)smem;   // reuse tile smem
    red[tid] = 0ULL;
    __syncthreads();

    // acc[im][jn][k]: row = warp_m*64 + im*16 + (lane>>2) + (k>=2 ? 8 : 0)
    //                col = bn0 + warp_n*64 + jn*8 + (lane&3)*2 + (k&1)
#pragma unroll
    for (int im = 0; im < 4; im++) {
#pragma unroll
        for (int half = 0; half < 2; half++) {
            unsigned long long key = 0ULL;
#pragma unroll
            for (int jn = 0; jn < 8; jn++) {
#pragma unroll
                for (int e = 0; e < 2; e++) {
                    int k = half * 2 + e;
                    int col = bn0 + warp_n * 64 + jn * 8 + (lane & 3) * 2 + e;
                    unsigned long long kk2 = pack_key(acc[im][jn][k], col);
                    if (kk2 > key) key = kk2;
                }
            }
            int row = warp_m * 64 + im * 16 + (lane >> 2) + half * 8;
            atomicMax(&red[row], key);
        }
    }
    __syncthreads();
    atomicMax(&g_best[bm0 + tid], red[tid]);
}

// out[b][c] = Wg[c][idx[b]]
__global__ void gather_kernel(const float* __restrict__ Wg, float* __restrict__ out) {
    __shared__ int s_idx;
    const int b = blockIdx.y;
    if (threadIdx.x == 0) {
        unsigned long long key = g_best[b];
        s_idx = (HID - 1) - (int)(unsigned int)(key & 0xFFFFFFFFu);
    }
    __syncthreads();
    const int c = blockIdx.x * blockDim.x + threadIdx.x;
    if (c < NCLS)
        out[(size_t)b * NCLS + c] = Wg[(size_t)c * HID + s_idx];
}

// ---------------- launch -------------------------------------------------------
extern "C" void kernel_launch(void* const* d_in, const int* in_sizes, int n_in,
                              void* d_out, int out_size) {
    const float* x  = (const float*)d_in[0];   // [BATCH, IN]
    const float* Wk = (const float*)d_in[1];   // [HID, IN]
    const float* Wg = (const float*)d_in[2];   // [NCLS, HID]
    float* out = (float*)d_out;                // [BATCH, NCLS]

    const int SMEM_BYTES = 1024 + ST * (int)STAGE_BYTES;   // align slack + 3 stages
    cudaFuncSetAttribute(gemm_argmax_mma, cudaFuncAttributeMaxDynamicSharedMemorySize, SMEM_BYTES);

    init_best_kernel<<<(BATCH + 255) / 256, 256>>>();
    convert_x_kernel<<<(BATCH * IN + 255) / 256, 256>>>(x);
    convert_w_kernel<<<(HID * IN + 255) / 256, 256>>>(Wk);

    gemm_argmax_mma<<<(BATCH / 256) * (HID / 128), 256, SMEM_BYTES>>>();

    dim3 sgrid((NCLS + 255) / 256, BATCH);
    gather_kernel<<<sgrid, 256>>>(Wg, out);
}

// round 6
// speedup vs baseline: 5.7893x; 2.0965x over previous
#include <cuda_runtime.h>
#include <cuda_fp16.h>
#include <cstdint>

#define BATCH 4096
#define IN    2048
#define HID   8192
#define NCLS  1000
#define KH    2048          // hi-only K
#define NCH   32            // KH / 64 k-chunks
#define ST    3             // pipeline stages
#define STAGE_BYTES 49152u  // A 32KB + B 16KB
#define MARGIN 0.5f
#define MAXCAND 64

// ---------------- scratch (static device arrays; no allocation) -------------
__device__ __align__(128) __half g_X[(size_t)BATCH * KH];    // hi(x)   [B, KH]
__device__ __align__(128) __half g_W[(size_t)HID   * KH];    // hi(Wk)  [HID, KH]
__device__ __align__(128) __half g_C[(size_t)BATCH * HID];   // approx scores, fp16
__device__ __align__(128) float  g_WgT[(size_t)HID * NCLS];  // Wg transposed
__device__ int g_idx[BATCH];

// ---------------- helpers ----------------------------------------------------
__device__ __forceinline__ uint32_t smem_u32(const void* p) {
    uint32_t a;
    asm("{ .reg .u64 t; cvta.to.shared.u64 t, %1; cvt.u32.u64 %0, t; }" : "=r"(a) : "l"(p));
    return a;
}
__device__ __forceinline__ void cp_async16(uint32_t dst, const void* src) {
    asm volatile("cp.async.cg.shared.global [%0], [%1], 16;" :: "r"(dst), "l"(src));
}
#define CP_COMMIT() asm volatile("cp.async.commit_group;" ::: "memory")
#define CP_WAIT(n)  asm volatile("cp.async.wait_group %0;" :: "n"(n) : "memory")

#define LDSM4(r0, r1, r2, r3, a)                                             \
    asm volatile("ldmatrix.sync.aligned.m8n8.x4.shared.b16 {%0,%1,%2,%3}, [%4];" \
                 : "=r"(r0), "=r"(r1), "=r"(r2), "=r"(r3) : "r"(a))

__device__ __forceinline__ void mma16816(float* c, const uint32_t* a, const uint32_t* b) {
    asm volatile(
        "mma.sync.aligned.m16n8k16.row.col.f32.f16.f16.f32 "
        "{%0,%1,%2,%3}, {%4,%5,%6,%7}, {%8,%9}, {%0,%1,%2,%3};"
        : "+f"(c[0]), "+f"(c[1]), "+f"(c[2]), "+f"(c[3])
        : "r"(a[0]), "r"(a[1]), "r"(a[2]), "r"(a[3]), "r"(b[0]), "r"(b[1]));
}

__device__ __forceinline__ uint32_t sw128(uint32_t off) { return off ^ ((off >> 3) & 0x70); }

// ---------------- conversion kernels ------------------------------------------
__global__ void convert_x_kernel(const float* __restrict__ x) {
    int i = blockIdx.x * blockDim.x + threadIdx.x;
    if (i < BATCH * KH) g_X[i] = __float2half_rn(x[i]);
}
__global__ void convert_w_kernel(const float* __restrict__ w) {
    int i = blockIdx.x * blockDim.x + threadIdx.x;
    if (i < HID * KH) g_W[i] = __float2half_rn(w[i]);
}

// ---------------- pass 1: fp16 GEMM (approx scores) ----------------------------
// C[b][h] = sum_k hi(x)[b][k] * hi(Wk)[h][k].  CTA tile 256x128, 3-stage
// cp.async pipeline, SW128 smem, 8 warps 4(m)x2(n), warp tile 64x64.
__global__ __launch_bounds__(256, 1)
void gemm_approx() {
    extern __shared__ char smem[];
    const int tid  = threadIdx.x;
    const int lane = tid & 31;
    const int wid  = tid >> 5;
    const int warp_m = wid >> 1;  // 0..3
    const int warp_n = wid & 1;   // 0..1

    int bid = blockIdx.x;
    int group = bid >> 7, within = bid & 127;
    int ncol = (group << 3) | (within & 7);   // 0..63
    int mrow = within >> 3;                   // 0..15
    const int bm0 = mrow * 256;
    const int bn0 = ncol * 128;

    uint32_t sb    = smem_u32(smem);
    uint32_t tiles = (sb + 1023) & ~1023u;

    const int row_l = tid >> 3;
    const int colb  = (tid & 7) * 16;
    uint32_t dswA[8];
#pragma unroll
    for (int i = 0; i < 8; i++) dswA[i] = sw128((row_l + 32 * i) * 128 + colb);

    const __half* pA = g_X + (size_t)(bm0 + row_l) * KH + (colb >> 1);
    const __half* pB = g_W + (size_t)(bn0 + row_l) * KH + (colb >> 1);

    const uint32_t aRow = warp_m * 64 + (lane & 15);
    const uint32_t aCol = (lane >> 4) << 4;
    const uint32_t bRow = warp_n * 64 + (lane & 7) + ((lane >> 4) << 3);
    const uint32_t bCol = ((lane >> 3) & 1) << 4;
    uint32_t aSwk[4], bSwk[4];
#pragma unroll
    for (int kk = 0; kk < 4; kk++) {
        aSwk[kk] = sw128(aRow * 128 + aCol + kk * 32);
        bSwk[kk] = sw128(bRow * 128 + bCol + kk * 32);
    }

    float acc[4][8][4];
#pragma unroll
    for (int i = 0; i < 4; i++)
#pragma unroll
        for (int j = 0; j < 8; j++)
#pragma unroll
            for (int k = 0; k < 4; k++) acc[i][j][k] = 0.0f;

#pragma unroll
    for (int p = 0; p < ST - 1; p++) {
        uint32_t As = tiles + p * STAGE_BYTES;
        uint32_t Bs = As + 32768u;
        size_t ko = (size_t)p * 64;
#pragma unroll
        for (int i = 0; i < 8; i++) cp_async16(As + dswA[i], pA + (size_t)i * 32 * KH + ko);
#pragma unroll
        for (int i = 0; i < 4; i++) cp_async16(Bs + dswA[i], pB + (size_t)i * 32 * KH + ko);
        CP_COMMIT();
    }

    for (int c = 0; c < NCH; c++) {
        const int s = c % ST;
        if (c + 2 < NCH) CP_WAIT(1); else CP_WAIT(0);
        __syncthreads();

        if (c + 2 < NCH) {
            const int cs = (c + 2) % ST;
            uint32_t As = tiles + cs * STAGE_BYTES;
            uint32_t Bs = As + 32768u;
            size_t ko = (size_t)(c + 2) * 64;
#pragma unroll
            for (int i = 0; i < 8; i++) cp_async16(As + dswA[i], pA + (size_t)i * 32 * KH + ko);
#pragma unroll
            for (int i = 0; i < 4; i++) cp_async16(Bs + dswA[i], pB + (size_t)i * 32 * KH + ko);
            CP_COMMIT();
        }

        const uint32_t aBase = tiles + s * STAGE_BYTES;
        const uint32_t bBase = aBase + 32768u;

#pragma unroll
        for (int kk = 0; kk < 4; kk++) {
            uint32_t a[4][4];
#pragma unroll
            for (int im = 0; im < 4; im++)
                LDSM4(a[im][0], a[im][1], a[im][2], a[im][3],
                      aBase + aSwk[kk] + im * 2048u);
            uint32_t b[8][2];
#pragma unroll
            for (int in2 = 0; in2 < 4; in2++) {
                uint32_t r0, r1, r2, r3;
                LDSM4(r0, r1, r2, r3, bBase + bSwk[kk] + in2 * 2048u);
                b[2 * in2][0] = r0;     b[2 * in2][1] = r1;
                b[2 * in2 + 1][0] = r2; b[2 * in2 + 1][1] = r3;
            }
#pragma unroll
            for (int im = 0; im < 4; im++)
#pragma unroll
                for (int jn = 0; jn < 8; jn++)
                    mma16816(acc[im][jn], a[im], b[jn]);
        }
    }

    // ---- epilogue: store approx scores as fp16 ----
    // acc[im][jn][k]: row = bm0 + warp_m*64 + im*16 + (lane>>2) + (k>=2 ? 8:0)
    //                 col = bn0 + warp_n*64 + jn*8 + (lane&3)*2 + (k&1)
#pragma unroll
    for (int im = 0; im < 4; im++) {
        int r0 = bm0 + warp_m * 64 + im * 16 + (lane >> 2);
#pragma unroll
        for (int jn = 0; jn < 8; jn++) {
            int col = bn0 + warp_n * 64 + jn * 8 + (lane & 3) * 2;
            __half2 v0 = __floats2half2_rn(acc[im][jn][0], acc[im][jn][1]);
            __half2 v1 = __floats2half2_rn(acc[im][jn][2], acc[im][jn][3]);
            *(__half2*)&g_C[(size_t)r0 * HID + col]       = v0;
            *(__half2*)&g_C[(size_t)(r0 + 8) * HID + col] = v1;
        }
    }
}

// ---------------- pass 2: per-row screen + exact fp32 refine -------------------
__global__ __launch_bounds__(256)
void refine_kernel(const float* __restrict__ x, const float* __restrict__ Wk) {
    __shared__ float xs[IN];          // 8KB: row of x
    __shared__ float red8[8];
    __shared__ float rowmax_s, tot_s;
    __shared__ int   cand[MAXCAND];
    __shared__ int   ncand;

    const int b    = blockIdx.x;
    const int tid  = threadIdx.x;
    const int lane = tid & 31;
    const int wid  = tid >> 5;

    if (tid == 0) ncand = 0;
    for (int i = tid; i < IN; i += 256) xs[i] = x[(size_t)b * IN + i];

    // row max of approx scores
    const __half2* crow = (const __half2*)(g_C + (size_t)b * HID);
    float m = -3.4e38f;
    for (int i = tid; i < HID / 2; i += 256) {
        __half2 v = crow[i];
        float a = __low2float(v), c = __high2float(v);
        m = fmaxf(m, fmaxf(a, c));
    }
#pragma unroll
    for (int o = 16; o > 0; o >>= 1) m = fmaxf(m, __shfl_xor_sync(0xffffffffu, m, o));
    if (lane == 0) red8[wid] = m;
    __syncthreads();
    if (tid == 0) {
        float mm = red8[0];
#pragma unroll
        for (int i = 1; i < 8; i++) mm = fmaxf(mm, red8[i]);
        rowmax_s = mm;
    }
    __syncthreads();
    const float thr = rowmax_s - MARGIN;

    // collect candidate columns
    for (int i = tid; i < HID / 2; i += 256) {
        __half2 v = crow[i];
        float a = __low2float(v), c = __high2float(v);
        if (a >= thr) { int p = atomicAdd(&ncand, 1); if (p < MAXCAND) cand[p] = 2 * i; }
        if (c >= thr) { int p = atomicAdd(&ncand, 1); if (p < MAXCAND) cand[p] = 2 * i + 1; }
    }
    __syncthreads();
    const int nc = min(ncand, MAXCAND);

    float bestv = -3.4e38f;
    int   besti = HID;
    for (int ci = 0; ci < nc; ci++) {
        const int h = cand[ci];
        const float* wr = Wk + (size_t)h * IN;
        float p = 0.0f;
        for (int k = tid; k < IN; k += 256) p = fmaf(xs[k], wr[k], p);
#pragma unroll
        for (int o = 16; o > 0; o >>= 1) p += __shfl_xor_sync(0xffffffffu, p, o);
        if (lane == 0) red8[wid] = p;
        __syncthreads();
        if (tid == 0) {
            float t = 0.0f;
#pragma unroll
            for (int i = 0; i < 8; i++) t += red8[i];
            tot_s = t;
        }
        __syncthreads();
        float tot = tot_s;
        if (tot > bestv || (tot == bestv && h < besti)) { bestv = tot; besti = h; }
        __syncthreads();   // red8/tot_s reuse
    }
    if (tid == 0) g_idx[b] = besti;
}

// ---------------- Wg transpose + gather ----------------------------------------
__global__ void transpose_wg_kernel(const float* __restrict__ Wg) {
    __shared__ float t[32][33];
    int h0 = blockIdx.x * 32;   // HID dim
    int c0 = blockIdx.y * 32;   // NCLS dim
    int txx = threadIdx.x, tyy = threadIdx.y;
    int c = c0 + tyy, h = h0 + txx;
    if (c < NCLS) t[tyy][txx] = Wg[(size_t)c * HID + h];
    __syncthreads();
    int ho = h0 + tyy, co = c0 + txx;
    if (co < NCLS) g_WgT[(size_t)ho * NCLS + co] = t[txx][tyy];
}

__global__ void gather_kernel(float* __restrict__ out) {
    const int b = blockIdx.x;
    const int idx = g_idx[b];
    const float* src = g_WgT + (size_t)idx * NCLS;
    for (int c = threadIdx.x; c < NCLS; c += 256)
        out[(size_t)b * NCLS + c] = src[c];
}

// ---------------- launch --------------------------------------------------------
extern "C" void kernel_launch(void* const* d_in, const int* in_sizes, int n_in,
                              void* d_out, int out_size) {
    const float* x  = (const float*)d_in[0];   // [BATCH, IN]
    const float* Wk = (const float*)d_in[1];   // [HID, IN]
    const float* Wg = (const float*)d_in[2];   // [NCLS, HID]
    float* out = (float*)d_out;                // [BATCH, NCLS]

    const int SMEM_BYTES = 1024 + ST * (int)STAGE_BYTES;
    cudaFuncSetAttribute(gemm_approx, cudaFuncAttributeMaxDynamicSharedMemorySize, SMEM_BYTES);

    convert_x_kernel<<<(BATCH * KH + 255) / 256, 256>>>(x);
    convert_w_kernel<<<(HID * KH + 255) / 256, 256>>>(Wk);

    gemm_approx<<<(BATCH / 256) * (HID / 128), 256, SMEM_BYTES>>>();

    refine_kernel<<<BATCH, 256>>>(x, Wk);

    dim3 tgrid(HID / 32, (NCLS + 31) / 32);
    transpose_wg_kernel<<<tgrid, dim3(32, 32)>>>(Wg);

    gather_kernel<<<BATCH, 256>>>(out);
}

// round 7
// speedup vs baseline: 5.8008x; 1.0020x over previous
#include <cuda_runtime.h>
#include <cuda_fp16.h>
#include <cstdint>

#define BATCH 4096
#define IN    2048
#define HID   8192
#define NCLS  1000
#define KH    2048          // hi-only K
#define NCH   32            // KH / 64 k-chunks
#define ST    3             // pipeline stages
#define STAGE_BYTES 49152u  // A 32KB + B 16KB
#define MARGIN 3.0f         // covers fp16-accum error (sigma ~0.2) with ~10x slack
#define MAXCAND 64

// ---------------- scratch (static device arrays; no allocation) -------------
__device__ __align__(128) __half g_X[(size_t)BATCH * KH];    // hi(x)   [B, KH]
__device__ __align__(128) __half g_W[(size_t)HID   * KH];    // hi(Wk)  [HID, KH]
__device__ __align__(128) __half g_C[(size_t)BATCH * HID];   // approx scores, fp16
__device__ __align__(128) float  g_WgT[(size_t)HID * NCLS];  // Wg transposed
__device__ int g_idx[BATCH];

// ---------------- helpers ----------------------------------------------------
__device__ __forceinline__ uint32_t smem_u32(const void* p) {
    uint32_t a;
    asm("{ .reg .u64 t; cvta.to.shared.u64 t, %1; cvt.u32.u64 %0, t; }" : "=r"(a) : "l"(p));
    return a;
}
__device__ __forceinline__ void cp_async16(uint32_t dst, const void* src) {
    asm volatile("cp.async.cg.shared.global [%0], [%1], 16;" :: "r"(dst), "l"(src));
}
#define CP_COMMIT() asm volatile("cp.async.commit_group;" ::: "memory")
#define CP_WAIT(n)  asm volatile("cp.async.wait_group %0;" :: "n"(n) : "memory")

#define LDSM4(r0, r1, r2, r3, a)                                             \
    asm volatile("ldmatrix.sync.aligned.m8n8.x4.shared.b16 {%0,%1,%2,%3}, [%4];" \
                 : "=r"(r0), "=r"(r1), "=r"(r2), "=r"(r3) : "r"(a))

// fp16-accumulate MMA: D(fp16) = A*B + C(fp16); c = {half2 row, half2 row+8}
__device__ __forceinline__ void mma16816_f16(uint32_t* c, const uint32_t* a, const uint32_t* b) {
    asm volatile(
        "mma.sync.aligned.m16n8k16.row.col.f16.f16.f16.f16 "
        "{%0,%1}, {%2,%3,%4,%5}, {%6,%7}, {%0,%1};"
        : "+r"(c[0]), "+r"(c[1])
        : "r"(a[0]), "r"(a[1]), "r"(a[2]), "r"(a[3]), "r"(b[0]), "r"(b[1]));
}

__device__ __forceinline__ uint32_t sw128(uint32_t off) { return off ^ ((off >> 3) & 0x70); }

// ---------------- conversion kernels ------------------------------------------
__global__ void convert_x_kernel(const float* __restrict__ x) {
    int i = blockIdx.x * blockDim.x + threadIdx.x;
    if (i < BATCH * KH) g_X[i] = __float2half_rn(x[i]);
}
__global__ void convert_w_kernel(const float* __restrict__ w) {
    int i = blockIdx.x * blockDim.x + threadIdx.x;
    if (i < HID * KH) g_W[i] = __float2half_rn(w[i]);
}

// ---------------- pass 1: fp16 GEMM (approx scores, fp16 accum) ----------------
// C[b][h] = sum_k hi(x)[b][k] * hi(Wk)[h][k].  CTA tile 256x128, 3-stage
// cp.async pipeline, SW128 smem, 8 warps 4(m)x2(n), warp tile 64x64.
__global__ __launch_bounds__(256, 1)
void gemm_approx() {
    extern __shared__ char smem[];
    const int tid  = threadIdx.x;
    const int lane = tid & 31;
    const int wid  = tid >> 5;
    const int warp_m = wid >> 1;  // 0..3
    const int warp_n = wid & 1;   // 0..1

    int bid = blockIdx.x;
    int group = bid >> 7, within = bid & 127;
    int ncol = (group << 3) | (within & 7);   // 0..63
    int mrow = within >> 3;                   // 0..15
    const int bm0 = mrow * 256;
    const int bn0 = ncol * 128;

    uint32_t sb    = smem_u32(smem);
    uint32_t tiles = (sb + 1023) & ~1023u;

    const int row_l = tid >> 3;
    const int colb  = (tid & 7) * 16;
    uint32_t dswA[8];
#pragma unroll
    for (int i = 0; i < 8; i++) dswA[i] = sw128((row_l + 32 * i) * 128 + colb);

    const __half* pA = g_X + (size_t)(bm0 + row_l) * KH + (colb >> 1);
    const __half* pB = g_W + (size_t)(bn0 + row_l) * KH + (colb >> 1);

    const uint32_t aRow = warp_m * 64 + (lane & 15);
    const uint32_t aCol = (lane >> 4) << 4;
    const uint32_t bRow = warp_n * 64 + (lane & 7) + ((lane >> 4) << 3);
    const uint32_t bCol = ((lane >> 3) & 1) << 4;
    uint32_t aSwk[4], bSwk[4];
#pragma unroll
    for (int kk = 0; kk < 4; kk++) {
        aSwk[kk] = sw128(aRow * 128 + aCol + kk * 32);
        bSwk[kk] = sw128(bRow * 128 + bCol + kk * 32);
    }

    uint32_t acc[4][8][2];   // fp16x2 accumulators
#pragma unroll
    for (int i = 0; i < 4; i++)
#pragma unroll
        for (int j = 0; j < 8; j++) { acc[i][j][0] = 0u; acc[i][j][1] = 0u; }

#pragma unroll
    for (int p = 0; p < ST - 1; p++) {
        uint32_t As = tiles + p * STAGE_BYTES;
        uint32_t Bs = As + 32768u;
        size_t ko = (size_t)p * 64;
#pragma unroll
        for (int i = 0; i < 8; i++) cp_async16(As + dswA[i], pA + (size_t)i * 32 * KH + ko);
#pragma unroll
        for (int i = 0; i < 4; i++) cp_async16(Bs + dswA[i], pB + (size_t)i * 32 * KH + ko);
        CP_COMMIT();
    }

    for (int c = 0; c < NCH; c++) {
        const int s = c % ST;
        if (c + 2 < NCH) CP_WAIT(1); else CP_WAIT(0);
        __syncthreads();

        if (c + 2 < NCH) {
            const int cs = (c + 2) % ST;
            uint32_t As = tiles + cs * STAGE_BYTES;
            uint32_t Bs = As + 32768u;
            size_t ko = (size_t)(c + 2) * 64;
#pragma unroll
            for (int i = 0; i < 8; i++) cp_async16(As + dswA[i], pA + (size_t)i * 32 * KH + ko);
#pragma unroll
            for (int i = 0; i < 4; i++) cp_async16(Bs + dswA[i], pB + (size_t)i * 32 * KH + ko);
            CP_COMMIT();
        }

        const uint32_t aBase = tiles + s * STAGE_BYTES;
        const uint32_t bBase = aBase + 32768u;

#pragma unroll
        for (int kk = 0; kk < 4; kk++) {
            uint32_t a[4][4];
#pragma unroll
            for (int im = 0; im < 4; im++)
                LDSM4(a[im][0], a[im][1], a[im][2], a[im][3],
                      aBase + aSwk[kk] + im * 2048u);
            uint32_t b[8][2];
#pragma unroll
            for (int in2 = 0; in2 < 4; in2++) {
                uint32_t r0, r1, r2, r3;
                LDSM4(r0, r1, r2, r3, bBase + bSwk[kk] + in2 * 2048u);
                b[2 * in2][0] = r0;     b[2 * in2][1] = r1;
                b[2 * in2 + 1][0] = r2; b[2 * in2 + 1][1] = r3;
            }
#pragma unroll
            for (int im = 0; im < 4; im++)
#pragma unroll
                for (int jn = 0; jn < 8; jn++)
                    mma16816_f16(acc[im][jn], a[im], b[jn]);
        }
    }

    // ---- epilogue: fp16 D fragments are already half2 in C layout ----
    // acc[im][jn][0] -> row r0,    cols col..col+1
    // acc[im][jn][1] -> row r0+8,  cols col..col+1
#pragma unroll
    for (int im = 0; im < 4; im++) {
        int r0 = bm0 + warp_m * 64 + im * 16 + (lane >> 2);
#pragma unroll
        for (int jn = 0; jn < 8; jn++) {
            int col = bn0 + warp_n * 64 + jn * 8 + (lane & 3) * 2;
            *(uint32_t*)&g_C[(size_t)r0 * HID + col]       = acc[im][jn][0];
            *(uint32_t*)&g_C[(size_t)(r0 + 8) * HID + col] = acc[im][jn][1];
        }
    }
}

// ---------------- pass 2: per-row screen + exact fp32 refine -------------------
__global__ __launch_bounds__(256)
void refine_kernel(const float* __restrict__ x, const float* __restrict__ Wk) {
    __shared__ float xs[IN];          // 8KB: row of x
    __shared__ float red8[8];
    __shared__ float rowmax_s, tot_s;
    __shared__ int   cand[MAXCAND];
    __shared__ int   ncand;

    const int b    = blockIdx.x;
    const int tid  = threadIdx.x;
    const int lane = tid & 31;
    const int wid  = tid >> 5;

    if (tid == 0) ncand = 0;
    for (int i = tid; i < IN; i += 256) xs[i] = x[(size_t)b * IN + i];

    // row max of approx scores
    const __half2* crow = (const __half2*)(g_C + (size_t)b * HID);
    float m = -3.4e38f;
    for (int i = tid; i < HID / 2; i += 256) {
        __half2 v = crow[i];
        float a = __low2float(v), c = __high2float(v);
        m = fmaxf(m, fmaxf(a, c));
    }
#pragma unroll
    for (int o = 16; o > 0; o >>= 1) m = fmaxf(m, __shfl_xor_sync(0xffffffffu, m, o));
    if (lane == 0) red8[wid] = m;
    __syncthreads();
    if (tid == 0) {
        float mm = red8[0];
#pragma unroll
        for (int i = 1; i < 8; i++) mm = fmaxf(mm, red8[i]);
        rowmax_s = mm;
    }
    __syncthreads();
    const float thr = rowmax_s - MARGIN;

    // collect candidate columns
    for (int i = tid; i < HID / 2; i += 256) {
        __half2 v = crow[i];
        float a = __low2float(v), c = __high2float(v);
        if (a >= thr) { int p = atomicAdd(&ncand, 1); if (p < MAXCAND) cand[p] = 2 * i; }
        if (c >= thr) { int p = atomicAdd(&ncand, 1); if (p < MAXCAND) cand[p] = 2 * i + 1; }
    }
    __syncthreads();
    const int nc = min(ncand, MAXCAND);

    float bestv = -3.4e38f;
    int   besti = HID;
    for (int ci = 0; ci < nc; ci++) {
        const int h = cand[ci];
        const float* wr = Wk + (size_t)h * IN;
        float p = 0.0f;
        for (int k = tid; k < IN; k += 256) p = fmaf(xs[k], wr[k], p);
#pragma unroll
        for (int o = 16; o > 0; o >>= 1) p += __shfl_xor_sync(0xffffffffu, p, o);
        if (lane == 0) red8[wid] = p;
        __syncthreads();
        if (tid == 0) {
            float t = 0.0f;
#pragma unroll
            for (int i = 0; i < 8; i++) t += red8[i];
            tot_s = t;
        }
        __syncthreads();
        float tot = tot_s;
        if (tot > bestv || (tot == bestv && h < besti)) { bestv = tot; besti = h; }
        __syncthreads();   // red8/tot_s reuse
    }
    if (tid == 0) g_idx[b] = besti;
}

// ---------------- Wg transpose + gather ----------------------------------------
__global__ void transpose_wg_kernel(const float* __restrict__ Wg) {
    __shared__ float t[32][33];
    int h0 = blockIdx.x * 32;   // HID dim
    int c0 = blockIdx.y * 32;   // NCLS dim
    int txx = threadIdx.x, tyy = threadIdx.y;
    int c = c0 + tyy, h = h0 + txx;
    if (c < NCLS) t[tyy][txx] = Wg[(size_t)c * HID + h];
    __syncthreads();
    int ho = h0 + tyy, co = c0 + txx;
    if (co < NCLS) g_WgT[(size_t)ho * NCLS + co] = t[txx][tyy];
}

__global__ void gather_kernel(float* __restrict__ out) {
    const int b = blockIdx.x;
    const int idx = g_idx[b];
    const float* src = g_WgT + (size_t)idx * NCLS;
    for (int c = threadIdx.x; c < NCLS; c += 256)
        out[(size_t)b * NCLS + c] = src[c];
}

// ---------------- launch --------------------------------------------------------
extern "C" void kernel_launch(void* const* d_in, const int* in_sizes, int n_in,
                              void* d_out, int out_size) {
    const float* x  = (const float*)d_in[0];   // [BATCH, IN]
    const float* Wk = (const float*)d_in[1];   // [HID, IN]
    const float* Wg = (const float*)d_in[2];   // [NCLS, HID]
    float* out = (float*)d_out;                // [BATCH, NCLS]

    const int SMEM_BYTES = 1024 + ST * (int)STAGE_BYTES;
    cudaFuncSetAttribute(gemm_approx, cudaFuncAttributeMaxDynamicSharedMemorySize, SMEM_BYTES);

    convert_x_kernel<<<(BATCH * KH + 255) / 256, 256>>>(x);
    convert_w_kernel<<<(HID * KH + 255) / 256, 256>>>(Wk);

    gemm_approx<<<(BATCH / 256) * (HID / 128), 256, SMEM_BYTES>>>();

    refine_kernel<<<BATCH, 256>>>(x, Wk);

    dim3 tgrid(HID / 32, (NCLS + 31) / 32);
    transpose_wg_kernel<<<tgrid, dim3(32, 32)>>>(Wg);

    gather_kernel<<<BATCH, 256>>>(out);
}